// round 14
// baseline (speedup 1.0000x reference)
#include <cuda_runtime.h>
#include <math_constants.h>
#include <cstdint>

#define NJ    17
#define H     512
#define W     512
#define HW    (H * W)
#define TOPK  30
#define ROWS  4
#define BANDS (H / ROWS)
#define ATHR  256

#define SH_CAP 16384   // entries held in shared for top-k merge (128 KB dynamic)

// ---------------- device scratch (no allocations allowed) ----------------
__device__ int   g_cnt[NJ];
__device__ float g_val[NJ][HW];
__device__ int   g_idx[NJ][HW];
__device__ float g_hx[NJ][TOPK];
__device__ float g_hy[NJ][TOPK];

// ---------------- stage 0: zero per-joint candidate counters ----------------
__global__ void k_zero() {
    if (threadIdx.x < NJ) g_cnt[threadIdx.x] = 0;
}

// ---------------- stage 1: 5x5 NMS (separable max) + candidate compaction ----
__global__ __launch_bounds__(ATHR) void k_nms(const float* __restrict__ heat) {
    __shared__ float s_tile[ROWS + 4][W];   // 16 KB
    __shared__ float s_vmax[ROWS][W];       //  8 KB
    __shared__ float s_pv[ROWS * W];        //  8 KB
    __shared__ int   s_pi[ROWS * W];        //  8 KB
    __shared__ int   s_cnt, s_base;

    const int j   = blockIdx.y;
    const int r0  = blockIdx.x * ROWS;
    const int tid = threadIdx.x;
    if (tid == 0) s_cnt = 0;

    const float* __restrict__ hj = heat + (size_t)j * HW;

    // load (ROWS+4) x 512 tile, -inf outside image
    #pragma unroll
    for (int idx = tid; idx < (ROWS + 4) * W; idx += ATHR) {
        int r = idx >> 9, c = idx & (W - 1);
        int g = r0 - 2 + r;
        s_tile[r][c] = (g >= 0 && g < H) ? hj[g * W + c] : -CUDART_INF_F;
    }
    __syncthreads();

    // vertical 5-max
    #pragma unroll
    for (int idx = tid; idx < ROWS * W; idx += ATHR) {
        int i = idx >> 9, c = idx & (W - 1);
        float m = s_tile[i][c];
        m = fmaxf(m, s_tile[i + 1][c]);
        m = fmaxf(m, s_tile[i + 2][c]);
        m = fmaxf(m, s_tile[i + 3][c]);
        m = fmaxf(m, s_tile[i + 4][c]);
        s_vmax[i][c] = m;
    }
    __syncthreads();

    // horizontal 5-max + keep test (value == window max)
    #pragma unroll
    for (int idx = tid; idx < ROWS * W; idx += ATHR) {
        int i = idx >> 9, c = idx & (W - 1);
        float v = s_tile[i + 2][c];
        float m = s_vmax[i][c];
        if (c >= 1)     m = fmaxf(m, s_vmax[i][c - 1]);
        if (c >= 2)     m = fmaxf(m, s_vmax[i][c - 2]);
        if (c <= W - 2) m = fmaxf(m, s_vmax[i][c + 1]);
        if (c <= W - 3) m = fmaxf(m, s_vmax[i][c + 2]);
        if (v == m) {
            int p = atomicAdd(&s_cnt, 1);
            s_pv[p] = v;
            s_pi[p] = ((r0 + i) << 9) | c;
        }
    }
    __syncthreads();

    if (tid == 0) s_base = atomicAdd(&g_cnt[j], s_cnt);
    __syncthreads();

    const int cnt = s_cnt, base = s_base;
    for (int p = tid; p < cnt; p += ATHR) {
        g_val[j][base + p] = s_pv[p];
        g_idx[j][base + p] = s_pi[p];
    }
}

// ---------------- stage 2: per-joint top-30 (value desc, index asc) + gather offsets
#define TTHR 512
extern __shared__ float s_dyn[];

__global__ __launch_bounds__(TTHR) void k_topk(const float* __restrict__ off,
                                               const int*   __restrict__ stride_p) {
    const int j   = blockIdx.x;
    const int tid = threadIdx.x;
    int cnt = g_cnt[j];
    if (cnt > HW) cnt = HW;

    float* sv = s_dyn;
    int*   si = (int*)(s_dyn + SH_CAP);
    const bool use_sh = (cnt <= SH_CAP);
    if (use_sh) {
        for (int p = tid; p < cnt; p += TTHR) {
            sv[p] = g_val[j][p];
            si[p] = g_idx[j][p];
        }
    }

    __shared__ float r_v[TTHR / 32];
    __shared__ int   r_i[TTHR / 32], r_p[TTHR / 32];

    // stride: tolerate int32 or float32 encoding of the scalar
    float sf;
    {
        int v = *stride_p;
        sf = (v > 0 && v < 1000000) ? (float)v : __int_as_float(v);
    }
    __syncthreads();

    for (int rank = 0; rank < TOPK; rank++) {
        float bv = -CUDART_INF_F;
        int   bi = 0x7fffffff, bp = -1;
        for (int p = tid; p < cnt; p += TTHR) {
            float v  = use_sh ? sv[p] : g_val[j][p];
            int   ii = use_sh ? si[p] : g_idx[j][p];
            if (v > bv || (v == bv && ii < bi)) { bv = v; bi = ii; bp = p; }
        }
        #pragma unroll
        for (int o = 16; o; o >>= 1) {
            float ov = __shfl_down_sync(0xffffffffu, bv, o);
            int   oi = __shfl_down_sync(0xffffffffu, bi, o);
            int   op = __shfl_down_sync(0xffffffffu, bp, o);
            if (ov > bv || (ov == bv && oi < bi)) { bv = ov; bi = oi; bp = op; }
        }
        const int warp = tid >> 5;
        if ((tid & 31) == 0) { r_v[warp] = bv; r_i[warp] = bi; r_p[warp] = bp; }
        __syncthreads();
        if (tid == 0) {
            #pragma unroll
            for (int w = 1; w < TTHR / 32; w++) {
                if (r_v[w] > bv || (r_v[w] == bv && r_i[w] < bi)) {
                    bv = r_v[w]; bi = r_i[w]; bp = r_p[w];
                }
            }
            if (bp >= 0 && bv > -CUDART_INF_F) {
                if (use_sh) sv[bp] = -CUDART_INF_F;
                else        g_val[j][bp] = -CUDART_INF_F;
                int   x  = bi & (W - 1);
                int   y  = bi >> 9;
                float ox = off[(size_t)(j * 2 + 0) * HW + bi];
                float oy = off[(size_t)(j * 2 + 1) * HW + bi];
                g_hx[j][rank] = __fmul_rn(sf, __fadd_rn((float)x, ox));
                g_hy[j][rank] = __fmul_rn(sf, __fadd_rn((float)y, oy));
            } else {
                g_hx[j][rank] = 0.0f;
                g_hy[j][rank] = 0.0f;
            }
        }
        __syncthreads();
    }
}

// ---------------- stage 3: nearest-candidate assignment -------------------
__global__ __launch_bounds__(256) void k_assign(const float2* __restrict__ poses,
                                                float2* __restrict__ out,
                                                int total) {
    __shared__ float sx[NJ][TOPK];
    __shared__ float sy[NJ][TOPK];
    for (int p = threadIdx.x; p < NJ * TOPK; p += 256) {
        int jj = p / TOPK, kk = p % TOPK;
        sx[jj][kk] = g_hx[jj][kk];
        sy[jj][kk] = g_hy[jj][kk];
    }
    __syncthreads();

    int gid = blockIdx.x * 256 + threadIdx.x;   // gid = n*17 + j
    if (gid >= total) return;
    const int j = gid % NJ;

    const float2 p = poses[gid];

    float d2s[TOPK];
    float m = CUDART_INF_F;
    #pragma unroll
    for (int k = 0; k < TOPK; k++) {
        float dx = __fsub_rn(p.x, sx[j][k]);
        float dy = __fsub_rn(p.y, sy[j][k]);
        float d2 = __fadd_rn(__fmul_rn(dx, dx), __fmul_rn(dy, dy));
        d2s[k] = d2;
        m = fminf(m, d2);
    }

    // reference argmins over sqrt(d2): find first k whose rounded sqrt equals
    // the minimal rounded sqrt (distinct d2 can collapse under sqrt rounding).
    const float s      = __fsqrt_rn(m);
    const float thresh = __fmul_rn(m, 1.000001f);   // covers sqrt preimage width (~2^-22 rel)
    int best = -1;
    #pragma unroll
    for (int k = 0; k < TOPK; k++) {
        if (best < 0 && d2s[k] <= thresh && __fsqrt_rn(d2s[k]) == s) best = k;
    }
    if (best < 0) best = 0;   // unreachable

    out[gid] = make_float2(sx[j][best], sy[j][best]);
}

// ---------------- launch --------------------------------------------------
extern "C" void kernel_launch(void* const* d_in, const int* in_sizes, int n_in,
                              void* d_out, int out_size) {
    const float* poses  = (const float*)d_in[0];
    const float* heat   = (const float*)d_in[1];
    const float* offs   = (const float*)d_in[2];
    const int*   stride = (const int*)d_in[3];

    const int N     = in_sizes[0] / (2 * NJ);
    const int total = N * NJ;

    cudaFuncSetAttribute(k_topk, cudaFuncAttributeMaxDynamicSharedMemorySize,
                         SH_CAP * 8);

    k_zero<<<1, 32>>>();
    dim3 g1(BANDS, NJ);
    k_nms<<<g1, ATHR>>>(heat);
    k_topk<<<NJ, TTHR, SH_CAP * 8>>>(offs, stride);
    k_assign<<<(total + 255) / 256, 256>>>((const float2*)poses,
                                           (float2*)d_out, total);
}

// round 15
// speedup vs baseline: 1.0068x; 1.0068x over previous
#include <cuda_runtime.h>
#include <math_constants.h>
#include <cstdint>

#define NJ    17
#define H     512
#define W     512
#define HW    (H * W)
#define TOPK  30
#define ROWS  4
#define BANDS (H / ROWS)
#define ATHR  256

#define SH_CAP 16384   // entries held in shared for top-k merge (128 KB dynamic)

// ---------------- device scratch (no allocations allowed) ----------------
__device__ int   g_cnt[NJ];
__device__ float g_val[NJ][HW];
__device__ int   g_idx[NJ][HW];
__device__ float g_hx[NJ][TOPK];
__device__ float g_hy[NJ][TOPK];

// ---------------- stage 0: zero per-joint candidate counters ----------------
__global__ void k_zero() {
    if (threadIdx.x < NJ) g_cnt[threadIdx.x] = 0;
}

// ---------------- stage 1: 5x5 NMS (separable max) + candidate compaction ----
__global__ __launch_bounds__(ATHR) void k_nms(const float* __restrict__ heat) {
    __shared__ float s_tile[ROWS + 4][W];   // 16 KB
    __shared__ float s_vmax[ROWS][W];       //  8 KB
    __shared__ float s_pv[ROWS * W];        //  8 KB
    __shared__ int   s_pi[ROWS * W];        //  8 KB
    __shared__ int   s_cnt, s_base;

    const int j   = blockIdx.y;
    const int r0  = blockIdx.x * ROWS;
    const int tid = threadIdx.x;
    if (tid == 0) s_cnt = 0;

    const float* __restrict__ hj = heat + (size_t)j * HW;

    // load (ROWS+4) x 512 tile, -inf outside image
    #pragma unroll
    for (int idx = tid; idx < (ROWS + 4) * W; idx += ATHR) {
        int r = idx >> 9, c = idx & (W - 1);
        int g = r0 - 2 + r;
        s_tile[r][c] = (g >= 0 && g < H) ? hj[g * W + c] : -CUDART_INF_F;
    }
    __syncthreads();

    // vertical 5-max
    #pragma unroll
    for (int idx = tid; idx < ROWS * W; idx += ATHR) {
        int i = idx >> 9, c = idx & (W - 1);
        float m = s_tile[i][c];
        m = fmaxf(m, s_tile[i + 1][c]);
        m = fmaxf(m, s_tile[i + 2][c]);
        m = fmaxf(m, s_tile[i + 3][c]);
        m = fmaxf(m, s_tile[i + 4][c]);
        s_vmax[i][c] = m;
    }
    __syncthreads();

    // horizontal 5-max + keep test (value == window max)
    #pragma unroll
    for (int idx = tid; idx < ROWS * W; idx += ATHR) {
        int i = idx >> 9, c = idx & (W - 1);
        float v = s_tile[i + 2][c];
        float m = s_vmax[i][c];
        if (c >= 1)     m = fmaxf(m, s_vmax[i][c - 1]);
        if (c >= 2)     m = fmaxf(m, s_vmax[i][c - 2]);
        if (c <= W - 2) m = fmaxf(m, s_vmax[i][c + 1]);
        if (c <= W - 3) m = fmaxf(m, s_vmax[i][c + 2]);
        if (v == m) {
            int p = atomicAdd(&s_cnt, 1);
            s_pv[p] = v;
            s_pi[p] = ((r0 + i) << 9) | c;
        }
    }
    __syncthreads();

    if (tid == 0) s_base = atomicAdd(&g_cnt[j], s_cnt);
    __syncthreads();

    const int cnt = s_cnt, base = s_base;
    for (int p = tid; p < cnt; p += ATHR) {
        g_val[j][base + p] = s_pv[p];
        g_idx[j][base + p] = s_pi[p];
    }
}

// ---------------- stage 2: per-joint top-30 (value desc, index asc) + gather offsets
#define TTHR 512
extern __shared__ float s_dyn[];

__global__ __launch_bounds__(TTHR) void k_topk(const float* __restrict__ off,
                                               const int*   __restrict__ stride_p) {
    const int j   = blockIdx.x;
    const int tid = threadIdx.x;
    int cnt = g_cnt[j];
    if (cnt > HW) cnt = HW;

    float* sv = s_dyn;
    int*   si = (int*)(s_dyn + SH_CAP);
    const bool use_sh = (cnt <= SH_CAP);
    if (use_sh) {
        for (int p = tid; p < cnt; p += TTHR) {
            sv[p] = g_val[j][p];
            si[p] = g_idx[j][p];
        }
    }

    __shared__ float r_v[TTHR / 32];
    __shared__ int   r_i[TTHR / 32], r_p[TTHR / 32];

    // stride: tolerate int32 or float32 encoding of the scalar
    float sf;
    {
        int v = *stride_p;
        sf = (v > 0 && v < 1000000) ? (float)v : __int_as_float(v);
    }
    __syncthreads();

    for (int rank = 0; rank < TOPK; rank++) {
        float bv = -CUDART_INF_F;
        int   bi = 0x7fffffff, bp = -1;
        for (int p = tid; p < cnt; p += TTHR) {
            float v  = use_sh ? sv[p] : g_val[j][p];
            int   ii = use_sh ? si[p] : g_idx[j][p];
            if (v > bv || (v == bv && ii < bi)) { bv = v; bi = ii; bp = p; }
        }
        #pragma unroll
        for (int o = 16; o; o >>= 1) {
            float ov = __shfl_down_sync(0xffffffffu, bv, o);
            int   oi = __shfl_down_sync(0xffffffffu, bi, o);
            int   op = __shfl_down_sync(0xffffffffu, bp, o);
            if (ov > bv || (ov == bv && oi < bi)) { bv = ov; bi = oi; bp = op; }
        }
        const int warp = tid >> 5;
        if ((tid & 31) == 0) { r_v[warp] = bv; r_i[warp] = bi; r_p[warp] = bp; }
        __syncthreads();
        if (tid == 0) {
            #pragma unroll
            for (int w = 1; w < TTHR / 32; w++) {
                if (r_v[w] > bv || (r_v[w] == bv && r_i[w] < bi)) {
                    bv = r_v[w]; bi = r_i[w]; bp = r_p[w];
                }
            }
            if (bp >= 0 && bv > -CUDART_INF_F) {
                if (use_sh) sv[bp] = -CUDART_INF_F;
                else        g_val[j][bp] = -CUDART_INF_F;
                int   x  = bi & (W - 1);
                int   y  = bi >> 9;
                float ox = off[(size_t)(j * 2 + 0) * HW + bi];
                float oy = off[(size_t)(j * 2 + 1) * HW + bi];
                g_hx[j][rank] = __fmul_rn(sf, __fadd_rn((float)x, ox));
                g_hy[j][rank] = __fmul_rn(sf, __fadd_rn((float)y, oy));
            } else {
                g_hx[j][rank] = 0.0f;
                g_hy[j][rank] = 0.0f;
            }
        }
        __syncthreads();
    }
}

// ---------------- stage 3: nearest-candidate assignment -------------------
__global__ __launch_bounds__(256) void k_assign(const float2* __restrict__ poses,
                                                float2* __restrict__ out,
                                                int total) {
    __shared__ float sx[NJ][TOPK];
    __shared__ float sy[NJ][TOPK];
    for (int p = threadIdx.x; p < NJ * TOPK; p += 256) {
        int jj = p / TOPK, kk = p % TOPK;
        sx[jj][kk] = g_hx[jj][kk];
        sy[jj][kk] = g_hy[jj][kk];
    }
    __syncthreads();

    int gid = blockIdx.x * 256 + threadIdx.x;   // gid = n*17 + j
    if (gid >= total) return;
    const int j = gid % NJ;

    const float2 p = poses[gid];

    float d2s[TOPK];
    float m = CUDART_INF_F;
    #pragma unroll
    for (int k = 0; k < TOPK; k++) {
        float dx = __fsub_rn(p.x, sx[j][k]);
        float dy = __fsub_rn(p.y, sy[j][k]);
        float d2 = __fadd_rn(__fmul_rn(dx, dx), __fmul_rn(dy, dy));
        d2s[k] = d2;
        m = fminf(m, d2);
    }

    // reference argmins over sqrt(d2): find first k whose rounded sqrt equals
    // the minimal rounded sqrt (distinct d2 can collapse under sqrt rounding).
    const float s      = __fsqrt_rn(m);
    const float thresh = __fmul_rn(m, 1.000001f);   // covers sqrt preimage width (~2^-22 rel)
    int best = -1;
    #pragma unroll
    for (int k = 0; k < TOPK; k++) {
        if (best < 0 && d2s[k] <= thresh && __fsqrt_rn(d2s[k]) == s) best = k;
    }
    if (best < 0) best = 0;   // unreachable

    out[gid] = make_float2(sx[j][best], sy[j][best]);
}

// ---------------- launch --------------------------------------------------
extern "C" void kernel_launch(void* const* d_in, const int* in_sizes, int n_in,
                              void* d_out, int out_size) {
    const float* poses  = (const float*)d_in[0];
    const float* heat   = (const float*)d_in[1];
    const float* offs   = (const float*)d_in[2];
    const int*   stride = (const int*)d_in[3];

    const int N     = in_sizes[0] / (2 * NJ);
    const int total = N * NJ;

    cudaFuncSetAttribute(k_topk, cudaFuncAttributeMaxDynamicSharedMemorySize,
                         SH_CAP * 8);

    k_zero<<<1, 32>>>();
    dim3 g1(BANDS, NJ);
    k_nms<<<g1, ATHR>>>(heat);
    k_topk<<<NJ, TTHR, SH_CAP * 8>>>(offs, stride);
    k_assign<<<(total + 255) / 256, 256>>>((const float2*)poses,
                                           (float2*)d_out, total);
}